// round 5
// baseline (speedup 1.0000x reference)
#include <cuda_runtime.h>
#include <cstddef>

#define SB 4
#define SS 1024
#define HID 768
#define NH 6
#define HD 64
#define AH 384
#define KS 9
#define PAD 4
#define BSROWS (SB*SS)
#define OUTW (2*AH)
#define NBH (SB*NH)

typedef unsigned long long ull;

// ---------------- scratch ----------------
__device__ float g_mq [BSROWS*AH];
__device__ float g_mk [BSROWS*AH];
__device__ float g_mv [BSROWS*AH];
__device__ float g_co [BSROWS*AH];
__device__ float g_dw [BSROWS*HID];
__device__ float g_ca [BSROWS*AH];
__device__ float g_ck [BSROWS*(NH*KS)];
__device__ float g_pwT[HID*AH];
__device__ float g_tdsm[SB*SS];
__device__ float g_sc [(size_t)NBH*SS*SS];   // 100.7 MB

// ---------------- f32x2 helpers ----------------
__device__ __forceinline__ ull pack2(float lo, float hi) {
    ull r; asm("mov.b64 %0, {%1, %2};" : "=l"(r) : "f"(lo), "f"(hi)); return r;
}
__device__ __forceinline__ void fma2(ull& d, ull a, ull b) {
    asm("fma.rn.f32x2 %0, %1, %2, %0;" : "+l"(d) : "l"(a), "l"(b));
}
__device__ __forceinline__ float2 unpack2(ull v) {
    float2 f; asm("mov.b64 {%0, %1}, %2;" : "=f"(f.x), "=f"(f.y) : "l"(v)); return f;
}
__device__ __forceinline__ ull ld_b64(const float* p) { return *reinterpret_cast<const ull*>(p); }

// ---------------- packed SGEMM: C[4096,384] = A[4096,K] @ B[K,384] ----------------
// tile 64(M) x 128(N), BK=16, 256 threads, per-thread 4x8 via FFMA2
// mode 0: C=acc; 1: C=acc+bias; 2: C=(acc+bias)*extra
template<int MODE>
__device__ __forceinline__ void gemm384_body(const float* __restrict__ A,
                                             const float* __restrict__ Bm,
                                             const float* __restrict__ bias,
                                             const float* __restrict__ extra,
                                             float* __restrict__ C, int K) {
    __shared__ float As[16][68];    // [k][m]
    __shared__ float Bs[16][128];   // [k][n]
    const int tid = threadIdx.x;
    const int tx = tid & 15, ty = tid >> 4;
    const int bm = blockIdx.y * 64, bn = blockIdx.x * 128;
    const int ar = tid >> 2, ac = (tid & 3) * 4;
    ull acc[4][4] = {};
    for (int k0 = 0; k0 < K; k0 += 16) {
        float4 av = *reinterpret_cast<const float4*>(&A[(size_t)(bm + ar) * K + k0 + ac]);
        As[ac + 0][ar] = av.x; As[ac + 1][ar] = av.y;
        As[ac + 2][ar] = av.z; As[ac + 3][ar] = av.w;
        #pragma unroll
        for (int u = 0; u < 2; u++) {
            int e = tid + 256 * u;
            int br = e >> 5, bc = (e & 31) * 4;
            *reinterpret_cast<float4*>(&Bs[br][bc]) =
                *reinterpret_cast<const float4*>(&Bm[(size_t)(k0 + br) * 384 + bn + bc]);
        }
        __syncthreads();
        #pragma unroll
        for (int kk = 0; kk < 16; kk++) {
            float4 a = *reinterpret_cast<const float4*>(&As[kk][ty * 4]);
            ull a0 = pack2(a.x, a.x), a1 = pack2(a.y, a.y);
            ull a2 = pack2(a.z, a.z), a3 = pack2(a.w, a.w);
            #pragma unroll
            for (int j = 0; j < 4; j++) {
                ull b = ld_b64(&Bs[kk][tx * 8 + 2 * j]);
                fma2(acc[0][j], a0, b);
                fma2(acc[1][j], a1, b);
                fma2(acc[2][j], a2, b);
                fma2(acc[3][j], a3, b);
            }
        }
        __syncthreads();
    }
    #pragma unroll
    for (int i = 0; i < 4; i++) {
        int gm = bm + ty * 4 + i;
        #pragma unroll
        for (int j = 0; j < 4; j++) {
            int gn = bn + tx * 8 + 2 * j;
            float2 f = unpack2(acc[i][j]);
            if (MODE >= 1) { f.x += bias[gn]; f.y += bias[gn + 1]; }
            if (MODE == 2) {
                f.x *= extra[(size_t)gm * 384 + gn];
                f.y *= extra[(size_t)gm * 384 + gn + 1];
            }
            *reinterpret_cast<float2*>(&C[(size_t)gm * 384 + gn]) = f;
        }
    }
}

__global__ __launch_bounds__(256) void k_gemm_mq(const float* A, const float* W) { gemm384_body<0>(A, W, nullptr, nullptr, g_mq, HID); }
__global__ __launch_bounds__(256) void k_gemm_mk(const float* A, const float* W) { gemm384_body<0>(A, W, nullptr, nullptr, g_mk, HID); }
__global__ __launch_bounds__(256) void k_gemm_mv(const float* A, const float* W) { gemm384_body<0>(A, W, nullptr, nullptr, g_mv, HID); }
__global__ __launch_bounds__(256) void k_gemm_co(const float* A, const float* W, const float* b) { gemm384_body<1>(A, W, b, nullptr, g_co, HID); }
__global__ __launch_bounds__(256) void k_gemm_mkc(const float* sep_b) { gemm384_body<2>(g_dw, g_pwT, sep_b, g_mq, g_ca, HID); }

// ---------------- small GEMM for ck (N=54) ----------------
__global__ __launch_bounds__(256) void k_gemm_ck(const float* __restrict__ Bm, const float* __restrict__ bias) {
    __shared__ float As[16][68];
    __shared__ float Bs[16][64];
    const int tid = threadIdx.x;
    const int tx = tid & 15, ty = tid >> 4;
    const int bm = blockIdx.y * 64, bn = 0;
    const int N = NH * KS, K = AH;
    float acc[4][4] = {};
    for (int k0 = 0; k0 < K; k0 += 16) {
        #pragma unroll
        for (int i = 0; i < 4; i++) {
            int e = tid + 256 * i;
            int r = e >> 4, c = e & 15;
            As[c][r] = g_ca[(size_t)(bm + r) * K + (k0 + c)];
            int r2 = e >> 6, c2 = e & 63;
            Bs[r2][c2] = (c2 < N) ? Bm[(size_t)(k0 + r2) * N + c2] : 0.f;
        }
        __syncthreads();
        #pragma unroll
        for (int kk = 0; kk < 16; kk++) {
            float a0 = As[kk][ty*4+0], a1 = As[kk][ty*4+1], a2 = As[kk][ty*4+2], a3 = As[kk][ty*4+3];
            float b0 = Bs[kk][tx*4+0], b1 = Bs[kk][tx*4+1], b2 = Bs[kk][tx*4+2], b3 = Bs[kk][tx*4+3];
            acc[0][0] += a0*b0; acc[0][1] += a0*b1; acc[0][2] += a0*b2; acc[0][3] += a0*b3;
            acc[1][0] += a1*b0; acc[1][1] += a1*b1; acc[1][2] += a1*b2; acc[1][3] += a1*b3;
            acc[2][0] += a2*b0; acc[2][1] += a2*b1; acc[2][2] += a2*b2; acc[2][3] += a2*b3;
            acc[3][0] += a3*b0; acc[3][1] += a3*b1; acc[3][2] += a3*b2; acc[3][3] += a3*b3;
        }
        __syncthreads();
    }
    #pragma unroll
    for (int i = 0; i < 4; i++) {
        int gm = bm + ty*4 + i;
        #pragma unroll
        for (int j = 0; j < 4; j++) {
            int gn = bn + tx*4 + j;
            if (gn < N) g_ck[(size_t)gm * N + gn] = acc[i][j] + bias[gn];
        }
    }
}

// ---------------- QK^T batched (f32x2): 64x64 tiles ----------------
__global__ __launch_bounds__(256) void qk_kernel() {
    const int bh = blockIdx.z;
    const int b = bh / NH, h = bh % NH;
    const int bi = blockIdx.y * 64, bj = blockIdx.x * 64;
    __shared__ float Qs[HD][68];
    __shared__ float Ks[HD][68];
    const int tid = threadIdx.x;
    const float* qb = g_mq + (size_t)b * SS * AH + h * HD;
    const float* kb = g_mk + (size_t)b * SS * AH + h * HD;
    #pragma unroll
    for (int r = 0; r < 16; r++) {
        int e = tid + 256 * r;
        int i = e >> 6, d = e & 63;
        Qs[d][i] = qb[(size_t)(bi + i) * AH + d];
        Ks[d][i] = kb[(size_t)(bj + i) * AH + d];
    }
    __syncthreads();
    const int tx = tid & 15, ty = tid >> 4;
    ull acc[4][2] = {};
    #pragma unroll 8
    for (int d = 0; d < HD; d++) {
        float4 a = *reinterpret_cast<const float4*>(&Qs[d][ty * 4]);
        ull a0 = pack2(a.x, a.x), a1 = pack2(a.y, a.y);
        ull a2 = pack2(a.z, a.z), a3 = pack2(a.w, a.w);
        #pragma unroll
        for (int j = 0; j < 2; j++) {
            ull bb = ld_b64(&Ks[d][tx * 4 + 2 * j]);
            fma2(acc[0][j], a0, bb);
            fma2(acc[1][j], a1, bb);
            fma2(acc[2][j], a2, bb);
            fma2(acc[3][j], a3, bb);
        }
    }
    float* crow = g_sc + (size_t)bh * SS * SS;
    #pragma unroll
    for (int i = 0; i < 4; i++) {
        size_t ro = (size_t)(bi + ty * 4 + i) * SS + bj + tx * 4;
        #pragma unroll
        for (int j = 0; j < 2; j++) {
            float2 f = unpack2(acc[i][j]);
            f.x *= 0.125f; f.y *= 0.125f;
            *reinterpret_cast<float2*>(&crow[ro + 2 * j]) = f;
        }
    }
}

// ---------------- P@V batched (f32x2): tile 128(M) x 64(N), BK=16 ----------------
__global__ __launch_bounds__(256) void pv_kernel(float* __restrict__ out) {
    const int bh = blockIdx.y;
    const int b = bh / NH, h = bh % NH;
    const int bi = blockIdx.x * 128;
    __shared__ float As[16][132];
    __shared__ float Bs[16][64];
    const int tid = threadIdx.x;
    const int tx = tid & 15, ty = tid >> 4;
    const float* P = g_sc + (size_t)bh * SS * SS;
    const float* vb = g_mv + (size_t)b * SS * AH + h * HD;
    ull acc[8][2] = {};
    const int br2 = tid >> 4, bc2 = (tid & 15) * 4;
    for (int k0 = 0; k0 < SS; k0 += 16) {
        #pragma unroll
        for (int u = 0; u < 2; u++) {
            int e = tid + 256 * u;
            int r = e >> 2, c4 = (e & 3) * 4;
            float4 av = *reinterpret_cast<const float4*>(&P[(size_t)(bi + r) * SS + k0 + c4]);
            As[c4 + 0][r] = av.x; As[c4 + 1][r] = av.y;
            As[c4 + 2][r] = av.z; As[c4 + 3][r] = av.w;
        }
        *reinterpret_cast<float4*>(&Bs[br2][bc2]) =
            *reinterpret_cast<const float4*>(&vb[(size_t)(k0 + br2) * AH + bc2]);
        __syncthreads();
        #pragma unroll
        for (int kk = 0; kk < 16; kk++) {
            float4 alo = *reinterpret_cast<const float4*>(&As[kk][ty * 8]);
            float4 ahi = *reinterpret_cast<const float4*>(&As[kk][ty * 8 + 4]);
            ull ad[8];
            ad[0] = pack2(alo.x, alo.x); ad[1] = pack2(alo.y, alo.y);
            ad[2] = pack2(alo.z, alo.z); ad[3] = pack2(alo.w, alo.w);
            ad[4] = pack2(ahi.x, ahi.x); ad[5] = pack2(ahi.y, ahi.y);
            ad[6] = pack2(ahi.z, ahi.z); ad[7] = pack2(ahi.w, ahi.w);
            #pragma unroll
            for (int j = 0; j < 2; j++) {
                ull bb = ld_b64(&Bs[kk][tx * 4 + 2 * j]);
                #pragma unroll
                for (int i = 0; i < 8; i++) fma2(acc[i][j], ad[i], bb);
            }
        }
        __syncthreads();
    }
    #pragma unroll
    for (int i = 0; i < 8; i++) {
        size_t ro = (size_t)(b * SS + bi + ty * 8 + i) * OUTW + h * HD + tx * 4;
        #pragma unroll
        for (int j = 0; j < 2; j++) {
            float2 f = unpack2(acc[i][j]);
            *reinterpret_cast<float2*>(&out[ro + 2 * j]) = f;
        }
    }
}

// ---------------- depthwise conv ----------------
__global__ void dwconv_kernel(const float* __restrict__ Kin, const float* __restrict__ dww) {
    int idx = blockIdx.x * blockDim.x + threadIdx.x;
    if (idx >= BSROWS * HID) return;
    int c = idx % HID;
    int s = (idx / HID) & (SS - 1);
    int b = idx / (HID * SS);
    float acc = 0.f;
    #pragma unroll
    for (int t = 0; t < KS; t++) {
        int sj = s + t - PAD;
        if (sj >= 0 && sj < SS)
            acc += Kin[((size_t)(b * SS + sj)) * HID + c] * dww[c * KS + t];
    }
    g_dw[idx] = acc;
}

__global__ void transpose_pw(const float* __restrict__ pw) {
    int idx = blockIdx.x * blockDim.x + threadIdx.x;
    if (idx >= HID * AH) return;
    int o = idx % AH, c = idx / AH;
    g_pwT[idx] = pw[(size_t)o * HID + c];
}

// ---------------- dynamic-span conv output ----------------
__global__ __launch_bounds__(384) void convout_kernel(float* __restrict__ out) {
    int bs = blockIdx.x;
    int tid = threadIdx.x;
    int h = tid >> 6, d = tid & 63;
    const float* cr = g_ck + (size_t)bs * (NH*KS) + h * KS;
    float w[KS];
    float mx = -3.4e38f;
    #pragma unroll
    for (int t = 0; t < KS; t++) { w[t] = cr[t]; mx = fmaxf(mx, w[t]); }
    float sm = 0.f;
    #pragma unroll
    for (int t = 0; t < KS; t++) { w[t] = __expf(w[t] - mx); sm += w[t]; }
    float inv = 1.f / sm;
    int b = bs >> 10, s = bs & (SS - 1);
    float acc = 0.f;
    #pragma unroll
    for (int t = 0; t < KS; t++) {
        int sj = s + t - PAD;
        if (sj >= 0 && sj < SS)
            acc += w[t] * inv * g_co[((size_t)(b * SS + sj)) * AH + h * HD + d];
    }
    out[(size_t)bs * OUTW + AH + h * HD + d] = acc;
}

// ---------------- td softmax ----------------
__global__ __launch_bounds__(256) void tdsm_kernel(const float* __restrict__ td, const int* __restrict__ mask) {
    int b = blockIdx.x;
    int tid = threadIdx.x;
    __shared__ float s_red[256];
    const float* tr = td + b * SS;
    const int* mr = mask + b * SS;
    float ss = 0.f;
    for (int j = tid; j < SS; j += 256) { float v = tr[j]; ss += v * v; }
    s_red[tid] = ss; __syncthreads();
    for (int off = 128; off > 0; off >>= 1) { if (tid < off) s_red[tid] += s_red[tid + off]; __syncthreads(); }
    float inv = 1.f / fmaxf(sqrtf(s_red[0]), 1e-12f);
    __syncthreads();
    float mx = -3.4e38f;
    for (int j = tid; j < SS; j += 256) { float v = mr[j] ? tr[j] * inv : -1e4f; mx = fmaxf(mx, v); }
    s_red[tid] = mx; __syncthreads();
    for (int off = 128; off > 0; off >>= 1) { if (tid < off) s_red[tid] = fmaxf(s_red[tid], s_red[tid + off]); __syncthreads(); }
    mx = s_red[0]; __syncthreads();
    float es = 0.f;
    for (int j = tid; j < SS; j += 256) { float v = mr[j] ? tr[j] * inv : -1e4f; es += __expf(v - mx); }
    s_red[tid] = es; __syncthreads();
    for (int off = 128; off > 0; off >>= 1) { if (tid < off) s_red[tid] += s_red[tid + off]; __syncthreads(); }
    es = s_red[0]; __syncthreads();
    float einv = 1.f / es;
    for (int j = tid; j < SS; j += 256) {
        float v = mr[j] ? tr[j] * inv : -1e4f;
        g_tdsm[b * SS + j] = __expf(v - mx) * einv;
    }
}

// ---------------- per-row pass: register-resident, shuffle reductions ----------------
__global__ __launch_bounds__(256) void row_kernel(const int* __restrict__ mask,
                                                  const float* __restrict__ gammas) {
    const int tid = threadIdx.x;
    const int lane = tid & 31, w = tid >> 5;
    const int row = blockIdx.x;
    const int i = row & (SS - 1);
    const int bh = row >> 10;
    const int h = bh % NH;
    const int b = bh / NH;

    __shared__ float s8[8];
    __shared__ float swarp[8];

    float* srow = g_sc + (size_t)row * SS;
    const int base = tid * 4;

    float4 sc = *reinterpret_cast<const float4*>(&srow[base]);
    int4  mk = *reinterpret_cast<const int4*>(&mask[b * SS + base]);

    // --- masked max ---
    float v0 = mk.x ? sc.x : -1e8f;
    float v1 = mk.y ? sc.y : -1e8f;
    float v2 = mk.z ? sc.z : -1e8f;
    float v3 = mk.w ? sc.w : -1e8f;
    float mx = fmaxf(fmaxf(v0, v1), fmaxf(v2, v3));
    #pragma unroll
    for (int o = 16; o > 0; o >>= 1) mx = fmaxf(mx, __shfl_xor_sync(0xffffffffu, mx, o));
    if (lane == 0) s8[w] = mx;
    __syncthreads();
    mx = fmaxf(fmaxf(fmaxf(s8[0], s8[1]), fmaxf(s8[2], s8[3])),
               fmaxf(fmaxf(s8[4], s8[5]), fmaxf(s8[6], s8[7])));

    // --- exp + sum ---
    float e0 = mk.x ? __expf(sc.x - mx) : 0.f;
    float e1 = mk.y ? __expf(sc.y - mx) : 0.f;
    float e2 = mk.z ? __expf(sc.z - mx) : 0.f;
    float e3 = mk.w ? __expf(sc.w - mx) : 0.f;
    float sm = (e0 + e1) + (e2 + e3);
    #pragma unroll
    for (int o = 16; o > 0; o >>= 1) sm += __shfl_xor_sync(0xffffffffu, sm, o);
    __syncthreads();                 // s8 reuse
    if (lane == 0) s8[w] = sm;
    __syncthreads();
    sm = ((s8[0] + s8[1]) + (s8[2] + s8[3])) + ((s8[4] + s8[5]) + (s8[6] + s8[7]));
    float inv = (sm > 0.f) ? (1.f / sm) : 0.f;

    // --- cumsum (thread-local 4 + warp scan + warp-total scan) ---
    float c0 = e0 * inv;
    float c1 = c0 + e1 * inv;
    float c2 = c1 + e2 * inv;
    float c3 = c2 + e3 * inv;
    float x = c3;
    #pragma unroll
    for (int o = 1; o < 32; o <<= 1) {
        float y = __shfl_up_sync(0xffffffffu, x, o);
        if (lane >= o) x += y;
    }
    if (lane == 31) swarp[w] = x;
    __syncthreads();
    if (tid < 8) {
        float t = swarp[tid];
        #pragma unroll
        for (int o = 1; o < 8; o <<= 1) {
            float y = __shfl_up_sync(0xffu, t, o);
            if (tid >= o) t += y;
        }
        swarp[tid] = t;
    }
    __syncthreads();
    float wpref = w ? swarp[w - 1] : 0.f;
    float total = swarp[7];
    float pref = x + wpref - c3;     // exclusive prefix before this thread's chunk

    float cum0 = pref + c0, cum1 = pref + c1, cum2 = pref + c2, cum3 = pref + c3;

    // --- distance decay ---
    const float gamma_h = -log1pf(__expf(gammas[h]));
    float4 tdv = *reinterpret_cast<const float4*>(&g_tdsm[b * SS + base]);
    float nv[4];
    float cums[4] = {cum0, cum1, cum2, cum3};
    float scs[4] = {sc.x, sc.y, sc.z, sc.w};
    int mks[4] = {mk.x, mk.y, mk.z, mk.w};
    float tds[4] = {tdv.x, tdv.y, tdv.z, tdv.w};
    float mx2 = -3.4e38f;
    #pragma unroll
    for (int u = 0; u < 4; u++) {
        int j = base + u;
        float rem = total - cums[u];
        float posd = fabsf((float)(j - i));
        float ds = sqrtf(fmaxf(rem * posd, 0.f));
        float te = __expf(ds * gamma_h);
        te = fminf(fmaxf(te, 1e-5f), 1e5f);
        if (j < i) te -= tds[u];
        float v = mks[u] ? scs[u] * te : -1e8f;
        nv[u] = v;
        mx2 = fmaxf(mx2, v);
    }
    #pragma unroll
    for (int o = 16; o > 0; o >>= 1) mx2 = fmaxf(mx2, __shfl_xor_sync(0xffffffffu, mx2, o));
    __syncthreads();
    if (lane == 0) s8[w] = mx2;
    __syncthreads();
    mx2 = fmaxf(fmaxf(fmaxf(s8[0], s8[1]), fmaxf(s8[2], s8[3])),
                fmaxf(fmaxf(s8[4], s8[5]), fmaxf(s8[6], s8[7])));

    float f0 = __expf(nv[0] - mx2);
    float f1 = __expf(nv[1] - mx2);
    float f2 = __expf(nv[2] - mx2);
    float f3 = __expf(nv[3] - mx2);
    float sm2 = (f0 + f1) + (f2 + f3);
    #pragma unroll
    for (int o = 16; o > 0; o >>= 1) sm2 += __shfl_xor_sync(0xffffffffu, sm2, o);
    __syncthreads();
    if (lane == 0) s8[w] = sm2;
    __syncthreads();
    sm2 = ((s8[0] + s8[1]) + (s8[2] + s8[3])) + ((s8[4] + s8[5]) + (s8[6] + s8[7]));
    float inv2 = 1.f / sm2;

    float4 outv = make_float4(f0 * inv2, f1 * inv2, f2 * inv2, f3 * inv2);
    *reinterpret_cast<float4*>(&srow[base]) = outv;
}

// ---------------- launch ----------------
extern "C" void kernel_launch(void* const* d_in, const int* in_sizes, int n_in,
                              void* d_out, int out_size) {
    const float* Q     = (const float*)d_in[0];
    const float* Kin   = (const float*)d_in[1];
    const float* V     = (const float*)d_in[2];
    const float* td    = (const float*)d_in[3];
    const int*   mask  = (const int*)  d_in[4];
    const float* Wq    = (const float*)d_in[5];
    const float* Wk    = (const float*)d_in[6];
    const float* Wv    = (const float*)d_in[7];
    const float* dw_w  = (const float*)d_in[8];
    const float* pw_w  = (const float*)d_in[9];
    const float* sep_b = (const float*)d_in[10];
    const float* ck_W  = (const float*)d_in[11];
    const float* ck_b  = (const float*)d_in[12];
    const float* co_W  = (const float*)d_in[13];
    const float* co_b  = (const float*)d_in[14];
    const float* gammas= (const float*)d_in[15];
    float* out = (float*)d_out;

    dim3 gg(3, 64);                            // 128-wide N tiles, 64-tall M tiles
    k_gemm_mq<<<gg, 256>>>(Q,   Wq);
    k_gemm_mk<<<gg, 256>>>(Kin, Wk);
    k_gemm_mv<<<gg, 256>>>(V,   Wv);
    k_gemm_co<<<gg, 256>>>(V,   co_W, co_b);

    dwconv_kernel<<<(BSROWS * HID + 255) / 256, 256>>>(Kin, dw_w);
    transpose_pw<<<(HID * AH + 255) / 256, 256>>>(pw_w);
    k_gemm_mkc<<<gg, 256>>>(sep_b);            // fused: (pw+sep_b)*mq -> g_ca

    k_gemm_ck<<<dim3(1, 64), 256>>>(ck_W, ck_b);
    convout_kernel<<<BSROWS, 384>>>(out);

    tdsm_kernel<<<SB, 256>>>(td, mask);
    qk_kernel<<<dim3(SS/64, SS/64, NBH), 256>>>();
    row_kernel<<<NBH * SS, 256>>>(mask, gammas);
    pv_kernel<<<dim3(SS/128, NBH), 256>>>(out);
}

// round 7
// speedup vs baseline: 1.3345x; 1.3345x over previous
#include <cuda_runtime.h>
#include <cstddef>

#define SB 4
#define SS 1024
#define HID 768
#define NH 6
#define HD 64
#define AH 384
#define KS 9
#define PAD 4
#define BSROWS (SB*SS)
#define OUTW (2*AH)
#define NBH (SB*NH)

// ---------------- scratch ----------------
__device__ float g_mq [BSROWS*AH];
__device__ float g_mk [BSROWS*AH];
__device__ float g_mv [BSROWS*AH];
__device__ float g_co [BSROWS*AH];
__device__ float g_dw [BSROWS*HID];
__device__ float g_ca [BSROWS*AH];
__device__ float g_ck [BSROWS*(NH*KS)];
__device__ float g_pwT[HID*AH];
__device__ float g_tdsm[SB*SS];
__device__ float g_sc [(size_t)NBH*SS*SS];   // 100.7 MB

// ---------------- generic tiled SGEMM body (R3-proven): 64x64 tile, BK=16 ----------------
// extra != nullptr: C = (acc + bias) * extra   (elementwise)
__device__ __forceinline__ void gemm64_body(const float* __restrict__ A,
                                            const float* __restrict__ Bm,
                                            const float* __restrict__ bias,
                                            const float* __restrict__ extra,
                                            float* __restrict__ C,
                                            int N, int K) {
    __shared__ float As[16][68];   // [k][m]
    __shared__ float Bs[16][64];   // [k][n]
    const int tid = threadIdx.x;           // 256 threads
    const int tx = tid & 15, ty = tid >> 4;
    const int bm = blockIdx.y * 64, bn = blockIdx.x * 64;
    float acc[4][4] = {};
    for (int k0 = 0; k0 < K; k0 += 16) {
        #pragma unroll
        for (int i = 0; i < 4; i++) {
            int e = tid + 256 * i;
            int r = e >> 4, c = e & 15;
            As[c][r] = A[(size_t)(bm + r) * K + (k0 + c)];
            int r2 = e >> 6, c2 = e & 63;
            int gn = bn + c2;
            Bs[r2][c2] = (gn < N) ? Bm[(size_t)(k0 + r2) * N + gn] : 0.f;
        }
        __syncthreads();
        #pragma unroll
        for (int kk = 0; kk < 16; kk++) {
            float a0 = As[kk][ty*4+0], a1 = As[kk][ty*4+1], a2 = As[kk][ty*4+2], a3 = As[kk][ty*4+3];
            float b0 = Bs[kk][tx*4+0], b1 = Bs[kk][tx*4+1], b2 = Bs[kk][tx*4+2], b3 = Bs[kk][tx*4+3];
            acc[0][0] += a0*b0; acc[0][1] += a0*b1; acc[0][2] += a0*b2; acc[0][3] += a0*b3;
            acc[1][0] += a1*b0; acc[1][1] += a1*b1; acc[1][2] += a1*b2; acc[1][3] += a1*b3;
            acc[2][0] += a2*b0; acc[2][1] += a2*b1; acc[2][2] += a2*b2; acc[2][3] += a2*b3;
            acc[3][0] += a3*b0; acc[3][1] += a3*b1; acc[3][2] += a3*b2; acc[3][3] += a3*b3;
        }
        __syncthreads();
    }
    #pragma unroll
    for (int i = 0; i < 4; i++) {
        int gm = bm + ty*4 + i;
        #pragma unroll
        for (int j = 0; j < 4; j++) {
            int gn = bn + tx*4 + j;
            if (gn < N) {
                float v = acc[i][j] + (bias ? bias[gn] : 0.f);
                if (extra) v *= extra[(size_t)gm * N + gn];
                C[(size_t)gm * N + gn] = v;
            }
        }
    }
}

// ---- merged projection GEMMs: blockIdx.z selects op (0:mq 1:mk 2:mv 3:co) ----
__global__ __launch_bounds__(256) void k_proj(const float* __restrict__ Q,
                                              const float* __restrict__ Kin,
                                              const float* __restrict__ V,
                                              const float* __restrict__ Wq,
                                              const float* __restrict__ Wk,
                                              const float* __restrict__ Wv,
                                              const float* __restrict__ coW,
                                              const float* __restrict__ cob) {
    const int op = blockIdx.z;
    const float* A = (op == 0) ? Q : (op == 1) ? Kin : V;
    const float* W = (op == 0) ? Wq : (op == 1) ? Wk : (op == 2) ? Wv : coW;
    const float* bias = (op == 3) ? cob : nullptr;
    float* C = (op == 0) ? g_mq : (op == 1) ? g_mk : (op == 2) ? g_mv : g_co;
    gemm64_body(A, W, bias, nullptr, C, AH, HID);
}

// mkc with fused elementwise multiply by mq -> writes conv_attn directly
__global__ __launch_bounds__(256) void k_gemm_mkc(const float* sep_b) {
    gemm64_body(g_dw, g_pwT, sep_b, g_mq, g_ca, AH, HID);
}
__global__ __launch_bounds__(256) void k_gemm_ck(const float* ckW, const float* ckb) {
    gemm64_body(g_ca, ckW, ckb, nullptr, g_ck, NH*KS, AH);
}

// ---------------- QK^T batched (R3-proven) ----------------
__global__ __launch_bounds__(256) void qk_kernel() {
    const int bh = blockIdx.z;
    const int b = bh / NH, h = bh % NH;
    const int bi = blockIdx.y * 64, bj = blockIdx.x * 64;
    __shared__ float Qs[HD][65];
    __shared__ float Ks[HD][65];
    const int tid = threadIdx.x;
    const float* qb = g_mq + (size_t)b * SS * AH + h * HD;
    const float* kb = g_mk + (size_t)b * SS * AH + h * HD;
    #pragma unroll
    for (int r = 0; r < 16; r++) {
        int e = tid + 256 * r;
        int i = e >> 6, d = e & 63;
        Qs[d][i] = qb[(size_t)(bi + i) * AH + d];
        Ks[d][i] = kb[(size_t)(bj + i) * AH + d];
    }
    __syncthreads();
    const int tx = tid & 15, ty = tid >> 4;
    float acc[4][4] = {};
    #pragma unroll 16
    for (int d = 0; d < HD; d++) {
        float a0 = Qs[d][ty*4+0], a1 = Qs[d][ty*4+1], a2 = Qs[d][ty*4+2], a3 = Qs[d][ty*4+3];
        float b0 = Ks[d][tx*4+0], b1 = Ks[d][tx*4+1], b2 = Ks[d][tx*4+2], b3 = Ks[d][tx*4+3];
        acc[0][0] += a0*b0; acc[0][1] += a0*b1; acc[0][2] += a0*b2; acc[0][3] += a0*b3;
        acc[1][0] += a1*b0; acc[1][1] += a1*b1; acc[1][2] += a1*b2; acc[1][3] += a1*b3;
        acc[2][0] += a2*b0; acc[2][1] += a2*b1; acc[2][2] += a2*b2; acc[2][3] += a2*b3;
        acc[3][0] += a3*b0; acc[3][1] += a3*b1; acc[3][2] += a3*b2; acc[3][3] += a3*b3;
    }
    float* crow = g_sc + ((size_t)bh * SS) * SS;
    #pragma unroll
    for (int i = 0; i < 4; i++) {
        size_t ro = (size_t)(bi + ty*4 + i) * SS + bj;
        #pragma unroll
        for (int j = 0; j < 4; j++)
            crow[ro + tx*4 + j] = acc[i][j] * 0.125f;
    }
}

// ---------------- P@V batched (R3-proven) ----------------
__global__ __launch_bounds__(256) void pv_kernel(float* __restrict__ out) {
    const int bh = blockIdx.y;
    const int b = bh / NH, h = bh % NH;
    const int bi = blockIdx.x * 64;
    __shared__ float As[16][68];
    __shared__ float Bs[16][64];
    const int tid = threadIdx.x;
    const int tx = tid & 15, ty = tid >> 4;
    const float* P = g_sc + (size_t)bh * SS * SS;
    const float* vb = g_mv + (size_t)b * SS * AH + h * HD;
    float acc[4][4] = {};
    for (int k0 = 0; k0 < SS; k0 += 16) {
        #pragma unroll
        for (int i = 0; i < 4; i++) {
            int e = tid + 256 * i;
            int r = e >> 4, c = e & 15;
            As[c][r] = P[(size_t)(bi + r) * SS + (k0 + c)];
            int r2 = e >> 6, c2 = e & 63;
            Bs[r2][c2] = vb[(size_t)(k0 + r2) * AH + c2];
        }
        __syncthreads();
        #pragma unroll
        for (int kk = 0; kk < 16; kk++) {
            float a0 = As[kk][ty*4+0], a1 = As[kk][ty*4+1], a2 = As[kk][ty*4+2], a3 = As[kk][ty*4+3];
            float b0 = Bs[kk][tx*4+0], b1 = Bs[kk][tx*4+1], b2 = Bs[kk][tx*4+2], b3 = Bs[kk][tx*4+3];
            acc[0][0] += a0*b0; acc[0][1] += a0*b1; acc[0][2] += a0*b2; acc[0][3] += a0*b3;
            acc[1][0] += a1*b0; acc[1][1] += a1*b1; acc[1][2] += a1*b2; acc[1][3] += a1*b3;
            acc[2][0] += a2*b0; acc[2][1] += a2*b1; acc[2][2] += a2*b2; acc[2][3] += a2*b3;
            acc[3][0] += a3*b0; acc[3][1] += a3*b1; acc[3][2] += a3*b2; acc[3][3] += a3*b3;
        }
        __syncthreads();
    }
    #pragma unroll
    for (int i = 0; i < 4; i++) {
        size_t ro = (size_t)(b * SS + bi + ty*4 + i) * OUTW + h * HD;
        #pragma unroll
        for (int j = 0; j < 4; j++)
            out[ro + tx*4 + j] = acc[i][j];
    }
}

// ---------------- depthwise conv ----------------
__global__ void dwconv_kernel(const float* __restrict__ Kin, const float* __restrict__ dww) {
    int idx = blockIdx.x * blockDim.x + threadIdx.x;
    if (idx >= BSROWS * HID) return;
    int c = idx % HID;
    int s = (idx / HID) & (SS - 1);
    int b = idx / (HID * SS);
    float acc = 0.f;
    #pragma unroll
    for (int t = 0; t < KS; t++) {
        int sj = s + t - PAD;
        if (sj >= 0 && sj < SS)
            acc += Kin[((size_t)(b * SS + sj)) * HID + c] * dww[c * KS + t];
    }
    g_dw[idx] = acc;
}

__global__ void transpose_pw(const float* __restrict__ pw) {
    int idx = blockIdx.x * blockDim.x + threadIdx.x;
    if (idx >= HID * AH) return;
    int o = idx % AH, c = idx / AH;
    g_pwT[idx] = pw[(size_t)o * HID + c];
}

// ---------------- dynamic-span conv output ----------------
__global__ __launch_bounds__(384) void convout_kernel(float* __restrict__ out) {
    int bs = blockIdx.x;
    int tid = threadIdx.x;
    int h = tid >> 6, d = tid & 63;
    const float* cr = g_ck + (size_t)bs * (NH*KS) + h * KS;
    float w[KS];
    float mx = -3.4e38f;
    #pragma unroll
    for (int t = 0; t < KS; t++) { w[t] = cr[t]; mx = fmaxf(mx, w[t]); }
    float sm = 0.f;
    #pragma unroll
    for (int t = 0; t < KS; t++) { w[t] = __expf(w[t] - mx); sm += w[t]; }
    float inv = 1.f / sm;
    int b = bs >> 10, s = bs & (SS - 1);
    float acc = 0.f;
    #pragma unroll
    for (int t = 0; t < KS; t++) {
        int sj = s + t - PAD;
        if (sj >= 0 && sj < SS)
            acc += w[t] * inv * g_co[((size_t)(b * SS + sj)) * AH + h * HD + d];
    }
    out[(size_t)bs * OUTW + AH + h * HD + d] = acc;
}

// ---------------- td softmax ----------------
__global__ __launch_bounds__(256) void tdsm_kernel(const float* __restrict__ td, const int* __restrict__ mask) {
    int b = blockIdx.x;
    int tid = threadIdx.x;
    __shared__ float s_red[256];
    const float* tr = td + b * SS;
    const int* mr = mask + b * SS;
    float ss = 0.f;
    for (int j = tid; j < SS; j += 256) { float v = tr[j]; ss += v * v; }
    s_red[tid] = ss; __syncthreads();
    for (int off = 128; off > 0; off >>= 1) { if (tid < off) s_red[tid] += s_red[tid + off]; __syncthreads(); }
    float inv = 1.f / fmaxf(sqrtf(s_red[0]), 1e-12f);
    __syncthreads();
    float mx = -3.4e38f;
    for (int j = tid; j < SS; j += 256) { float v = mr[j] ? tr[j] * inv : -1e4f; mx = fmaxf(mx, v); }
    s_red[tid] = mx; __syncthreads();
    for (int off = 128; off > 0; off >>= 1) { if (tid < off) s_red[tid] = fmaxf(s_red[tid], s_red[tid + off]); __syncthreads(); }
    mx = s_red[0]; __syncthreads();
    float es = 0.f;
    for (int j = tid; j < SS; j += 256) { float v = mr[j] ? tr[j] * inv : -1e4f; es += __expf(v - mx); }
    s_red[tid] = es; __syncthreads();
    for (int off = 128; off > 0; off >>= 1) { if (tid < off) s_red[tid] += s_red[tid + off]; __syncthreads(); }
    es = s_red[0]; __syncthreads();
    float einv = 1.f / es;
    for (int j = tid; j < SS; j += 256) {
        float v = mr[j] ? tr[j] * inv : -1e4f;
        g_tdsm[b * SS + j] = __expf(v - mx) * einv;
    }
}

// ---------------- per-row pass (R5-proven register/shuffle version) ----------------
__global__ __launch_bounds__(256) void row_kernel(const int* __restrict__ mask,
                                                  const float* __restrict__ gammas) {
    const int tid = threadIdx.x;
    const int lane = tid & 31, w = tid >> 5;
    const int row = blockIdx.x;
    const int i = row & (SS - 1);
    const int bh = row >> 10;
    const int h = bh % NH;
    const int b = bh / NH;

    __shared__ float s8[8];
    __shared__ float swarp[8];

    float* srow = g_sc + (size_t)row * SS;
    const int base = tid * 4;

    float4 sc = *reinterpret_cast<const float4*>(&srow[base]);
    int4  mk = *reinterpret_cast<const int4*>(&mask[b * SS + base]);

    float v0 = mk.x ? sc.x : -1e8f;
    float v1 = mk.y ? sc.y : -1e8f;
    float v2 = mk.z ? sc.z : -1e8f;
    float v3 = mk.w ? sc.w : -1e8f;
    float mx = fmaxf(fmaxf(v0, v1), fmaxf(v2, v3));
    #pragma unroll
    for (int o = 16; o > 0; o >>= 1) mx = fmaxf(mx, __shfl_xor_sync(0xffffffffu, mx, o));
    if (lane == 0) s8[w] = mx;
    __syncthreads();
    mx = fmaxf(fmaxf(fmaxf(s8[0], s8[1]), fmaxf(s8[2], s8[3])),
               fmaxf(fmaxf(s8[4], s8[5]), fmaxf(s8[6], s8[7])));

    float e0 = mk.x ? __expf(sc.x - mx) : 0.f;
    float e1 = mk.y ? __expf(sc.y - mx) : 0.f;
    float e2 = mk.z ? __expf(sc.z - mx) : 0.f;
    float e3 = mk.w ? __expf(sc.w - mx) : 0.f;
    float sm = (e0 + e1) + (e2 + e3);
    #pragma unroll
    for (int o = 16; o > 0; o >>= 1) sm += __shfl_xor_sync(0xffffffffu, sm, o);
    __syncthreads();
    if (lane == 0) s8[w] = sm;
    __syncthreads();
    sm = ((s8[0] + s8[1]) + (s8[2] + s8[3])) + ((s8[4] + s8[5]) + (s8[6] + s8[7]));
    float inv = (sm > 0.f) ? (1.f / sm) : 0.f;

    float c0 = e0 * inv;
    float c1 = c0 + e1 * inv;
    float c2 = c1 + e2 * inv;
    float c3 = c2 + e3 * inv;
    float x = c3;
    #pragma unroll
    for (int o = 1; o < 32; o <<= 1) {
        float y = __shfl_up_sync(0xffffffffu, x, o);
        if (lane >= o) x += y;
    }
    if (lane == 31) swarp[w] = x;
    __syncthreads();
    if (tid < 8) {
        float t = swarp[tid];
        #pragma unroll
        for (int o = 1; o < 8; o <<= 1) {
            float y = __shfl_up_sync(0xffu, t, o);
            if (tid >= o) t += y;
        }
        swarp[tid] = t;
    }
    __syncthreads();
    float wpref = w ? swarp[w - 1] : 0.f;
    float total = swarp[7];
    float pref = x + wpref - c3;

    float cums[4] = {pref + c0, pref + c1, pref + c2, pref + c3};

    const float gamma_h = -log1pf(__expf(gammas[h]));
    float4 tdv = *reinterpret_cast<const float4*>(&g_tdsm[b * SS + base]);
    float nv[4];
    float scs[4] = {sc.x, sc.y, sc.z, sc.w};
    int mks[4] = {mk.x, mk.y, mk.z, mk.w};
    float tds[4] = {tdv.x, tdv.y, tdv.z, tdv.w};
    float mx2 = -3.4e38f;
    #pragma unroll
    for (int u = 0; u < 4; u++) {
        int j = base + u;
        float rem = total - cums[u];
        float posd = fabsf((float)(j - i));
        float ds = sqrtf(fmaxf(rem * posd, 0.f));
        float te = __expf(ds * gamma_h);
        te = fminf(fmaxf(te, 1e-5f), 1e5f);
        if (j < i) te -= tds[u];
        float v = mks[u] ? scs[u] * te : -1e8f;
        nv[u] = v;
        mx2 = fmaxf(mx2, v);
    }
    #pragma unroll
    for (int o = 16; o > 0; o >>= 1) mx2 = fmaxf(mx2, __shfl_xor_sync(0xffffffffu, mx2, o));
    __syncthreads();
    if (lane == 0) s8[w] = mx2;
    __syncthreads();
    mx2 = fmaxf(fmaxf(fmaxf(s8[0], s8[1]), fmaxf(s8[2], s8[3])),
                fmaxf(fmaxf(s8[4], s8[5]), fmaxf(s8[6], s8[7])));

    float f0 = __expf(nv[0] - mx2);
    float f1 = __expf(nv[1] - mx2);
    float f2 = __expf(nv[2] - mx2);
    float f3 = __expf(nv[3] - mx2);
    float sm2 = (f0 + f1) + (f2 + f3);
    #pragma unroll
    for (int o = 16; o > 0; o >>= 1) sm2 += __shfl_xor_sync(0xffffffffu, sm2, o);
    __syncthreads();
    if (lane == 0) s8[w] = sm2;
    __syncthreads();
    sm2 = ((s8[0] + s8[1]) + (s8[2] + s8[3])) + ((s8[4] + s8[5]) + (s8[6] + s8[7]));
    float inv2 = 1.f / sm2;

    float4 outv = make_float4(f0 * inv2, f1 * inv2, f2 * inv2, f3 * inv2);
    *reinterpret_cast<float4*>(&srow[base]) = outv;
}

// ---------------- launch ----------------
extern "C" void kernel_launch(void* const* d_in, const int* in_sizes, int n_in,
                              void* d_out, int out_size) {
    const float* Q     = (const float*)d_in[0];
    const float* Kin   = (const float*)d_in[1];
    const float* V     = (const float*)d_in[2];
    const float* td    = (const float*)d_in[3];
    const int*   mask  = (const int*)  d_in[4];
    const float* Wq    = (const float*)d_in[5];
    const float* Wk    = (const float*)d_in[6];
    const float* Wv    = (const float*)d_in[7];
    const float* dw_w  = (const float*)d_in[8];
    const float* pw_w  = (const float*)d_in[9];
    const float* sep_b = (const float*)d_in[10];
    const float* ck_W  = (const float*)d_in[11];
    const float* ck_b  = (const float*)d_in[12];
    const float* co_W  = (const float*)d_in[13];
    const float* co_b  = (const float*)d_in[14];
    const float* gammas= (const float*)d_in[15];
    float* out = (float*)d_out;

    // prep for mkc (independent of projections)
    dwconv_kernel<<<(BSROWS * HID + 255) / 256, 256>>>(Kin, dw_w);
    transpose_pw<<<(HID * AH + 255) / 256, 256>>>(pw_w);

    // all four 768-K projections in one launch: grid 6x64x4 = 1536 blocks
    k_proj<<<dim3(AH/64, BSROWS/64, 4), 256>>>(Q, Kin, V, Wq, Wk, Wv, co_W, co_b);

    // mkc GEMM fused with *mq -> g_ca
    k_gemm_mkc<<<dim3(AH/64, BSROWS/64), 256>>>(sep_b);

    k_gemm_ck<<<dim3(1, BSROWS/64), 256>>>(ck_W, ck_b);
    convout_kernel<<<BSROWS, 384>>>(out);

    tdsm_kernel<<<SB, 256>>>(td, mask);
    qk_kernel<<<dim3(SS/64, SS/64, NBH), 256>>>();
    row_kernel<<<NBH * SS, 256>>>(mask, gammas);
    pv_kernel<<<dim3(SS/64, NBH), 256>>>(out);
}

// round 12
// speedup vs baseline: 1.9460x; 1.4583x over previous
#include <cuda_runtime.h>
#include <cstddef>
#include <cstdint>

#define SB 4
#define SS 1024
#define HID 768
#define NH 6
#define HD 64
#define AH 384
#define KS 9
#define PAD 4
#define BSROWS (SB*SS)
#define OUTW (2*AH)
#define NBH (SB*NH)
#define NCK (NH*KS)   // 54

// ---------------- scratch ----------------
__device__ float g_mq [BSROWS*AH];
__device__ float g_mk [BSROWS*AH];
__device__ float g_mv [BSROWS*AH];
__device__ float g_co [BSROWS*AH];
__device__ float g_mkc[BSROWS*AH];
__device__ float g_dw [BSROWS*HID];
__device__ float g_ck [BSROWS*NCK];
__device__ float g_pwT[HID*AH];
__device__ float g_tdsm[SB*SS];
__device__ float g_sc [(size_t)NBH*SS*SS];   // 100.7 MB

// ---------------- tf32 mma helpers ----------------
__device__ __forceinline__ unsigned f2tf(float x) {
    unsigned r; asm("cvt.rna.tf32.f32 %0, %1;" : "=r"(r) : "f"(x)); return r;
}
__device__ __forceinline__ void mma8(float c[4], unsigned a0, unsigned a1, unsigned a2, unsigned a3,
                                     unsigned b0, unsigned b1) {
    asm volatile("mma.sync.aligned.m16n8k8.row.col.f32.tf32.tf32.f32 "
        "{%0,%1,%2,%3}, {%4,%5,%6,%7}, {%8,%9}, {%0,%1,%2,%3};"
        : "+f"(c[0]), "+f"(c[1]), "+f"(c[2]), "+f"(c[3])
        : "r"(a0), "r"(a1), "r"(a2), "r"(a3), "r"(b0), "r"(b1));
}

// ---------------- unified tf32 GEMM body ----------------
// C_tile(64x64) = A[64xK] @ B ;  A row-major (lda), optional elementwise A2 multiplier.
// BT=false: B is K x N row-major (ldb). BT=true: B is N x K row-major (ldb) (i.e. B^T used).
// SPLIT=true: 3xTF32 hi/lo decomposition (fp32-grade accuracy).
// Nb: valid N inside the 64-wide tile (<=64); OOB filled with zeros.
template<bool BT, bool SPLIT>
__device__ __forceinline__ void tf32_gemm(const float* __restrict__ A, int lda,
                                          const float* __restrict__ A2,
                                          const float* __restrict__ B, int ldb,
                                          int K, int Nb, float c[2][2][4]) {
    __shared__ unsigned AsH[64][20];
    __shared__ unsigned AsL[SPLIT ? 64 : 1][20];
    __shared__ unsigned BsH[16][72];
    __shared__ unsigned BsL[SPLIT ? 16 : 1][72];

    const int t = threadIdx.x;
    const int bm = blockIdx.y * 64, bn = blockIdx.x * 64;
    const int am = t >> 2, ak = (t & 3) * 4;
    const int wid = t >> 5, lane = t & 31;
    const int wm = wid >> 2, wn = wid & 3;
    const int r = lane >> 2, cl = lane & 3;

    #pragma unroll
    for (int mt = 0; mt < 2; mt++)
        #pragma unroll
        for (int nt = 0; nt < 2; nt++)
            #pragma unroll
            for (int u = 0; u < 4; u++) c[mt][nt][u] = 0.f;

    for (int k0 = 0; k0 < K; k0 += 16) {
        __syncthreads();
        // ---- A tile: As[m][k], one float4 per thread ----
        {
            size_t off = (size_t)(bm + am) * lda + k0 + ak;
            float4 v = *reinterpret_cast<const float4*>(A + off);
            if (A2) {
                float4 w = *reinterpret_cast<const float4*>(A2 + off);
                v.x *= w.x; v.y *= w.y; v.z *= w.z; v.w *= w.w;
            }
            uint4 h; h.x = f2tf(v.x); h.y = f2tf(v.y); h.z = f2tf(v.z); h.w = f2tf(v.w);
            *reinterpret_cast<uint4*>(&AsH[am][ak]) = h;
            if (SPLIT) {
                uint4 l;
                l.x = f2tf(v.x - __uint_as_float(h.x));
                l.y = f2tf(v.y - __uint_as_float(h.y));
                l.z = f2tf(v.z - __uint_as_float(h.z));
                l.w = f2tf(v.w - __uint_as_float(h.w));
                *reinterpret_cast<uint4*>(&AsL[am][ak]) = l;
            }
        }
        // ---- B tile: Bs[k][n] ----
        if (!BT) {
            int bk = t >> 4, bn4 = (t & 15) * 4;
            const float* bp = B + (size_t)(k0 + bk) * ldb + bn4;   // bn==0 tiles use blockIdx.x==0? no: add bn
            bp += bn;
            float4 v;
            if (Nb == 64) {
                v = *reinterpret_cast<const float4*>(bp);
            } else {
                v.x = (bn4 + 0 < Nb) ? bp[0] : 0.f;
                v.y = (bn4 + 1 < Nb) ? bp[1] : 0.f;
                v.z = (bn4 + 2 < Nb) ? bp[2] : 0.f;
                v.w = (bn4 + 3 < Nb) ? bp[3] : 0.f;
            }
            uint4 h; h.x = f2tf(v.x); h.y = f2tf(v.y); h.z = f2tf(v.z); h.w = f2tf(v.w);
            *reinterpret_cast<uint4*>(&BsH[bk][bn4]) = h;
            if (SPLIT) {
                uint4 l;
                l.x = f2tf(v.x - __uint_as_float(h.x));
                l.y = f2tf(v.y - __uint_as_float(h.y));
                l.z = f2tf(v.z - __uint_as_float(h.z));
                l.w = f2tf(v.w - __uint_as_float(h.w));
                *reinterpret_cast<uint4*>(&BsL[bk][bn4]) = l;
            }
        } else {
            int n = t >> 2, k4 = (t & 3) * 4;
            float4 v = *reinterpret_cast<const float4*>(B + (size_t)(bn + n) * ldb + k0 + k4);
            BsH[k4 + 0][n] = f2tf(v.x);
            BsH[k4 + 1][n] = f2tf(v.y);
            BsH[k4 + 2][n] = f2tf(v.z);
            BsH[k4 + 3][n] = f2tf(v.w);
            if (SPLIT) {
                BsL[k4 + 0][n] = f2tf(v.x - __uint_as_float(BsH[k4 + 0][n]));
                BsL[k4 + 1][n] = f2tf(v.y - __uint_as_float(BsH[k4 + 1][n]));
                BsL[k4 + 2][n] = f2tf(v.z - __uint_as_float(BsH[k4 + 2][n]));
                BsL[k4 + 3][n] = f2tf(v.w - __uint_as_float(BsH[k4 + 3][n]));
            }
        }
        __syncthreads();

        #pragma unroll
        for (int k8 = 0; k8 < 16; k8 += 8) {
            unsigned aH[2][4], bH[2][2];
            unsigned aL[2][4], bL[2][2];
            #pragma unroll
            for (int mt = 0; mt < 2; mt++) {
                int mr = wm * 32 + mt * 16 + r;
                aH[mt][0] = AsH[mr][k8 + cl];
                aH[mt][1] = AsH[mr + 8][k8 + cl];
                aH[mt][2] = AsH[mr][k8 + cl + 4];
                aH[mt][3] = AsH[mr + 8][k8 + cl + 4];
                if (SPLIT) {
                    aL[mt][0] = AsL[mr][k8 + cl];
                    aL[mt][1] = AsL[mr + 8][k8 + cl];
                    aL[mt][2] = AsL[mr][k8 + cl + 4];
                    aL[mt][3] = AsL[mr + 8][k8 + cl + 4];
                }
            }
            #pragma unroll
            for (int nt = 0; nt < 2; nt++) {
                int bc = wn * 16 + nt * 8 + r;
                bH[nt][0] = BsH[k8 + cl][bc];
                bH[nt][1] = BsH[k8 + cl + 4][bc];
                if (SPLIT) {
                    bL[nt][0] = BsL[k8 + cl][bc];
                    bL[nt][1] = BsL[k8 + cl + 4][bc];
                }
            }
            #pragma unroll
            for (int mt = 0; mt < 2; mt++)
                #pragma unroll
                for (int nt = 0; nt < 2; nt++) {
                    mma8(c[mt][nt], aH[mt][0], aH[mt][1], aH[mt][2], aH[mt][3], bH[nt][0], bH[nt][1]);
                    if (SPLIT) {
                        mma8(c[mt][nt], aH[mt][0], aH[mt][1], aH[mt][2], aH[mt][3], bL[nt][0], bL[nt][1]);
                        mma8(c[mt][nt], aL[mt][0], aL[mt][1], aL[mt][2], aL[mt][3], bH[nt][0], bH[nt][1]);
                    }
                }
        }
    }
}

// ---- 5 projection GEMMs (3xTF32 split): op = blockIdx.z ----
__global__ __launch_bounds__(256) void k_proj_tc(const float* __restrict__ Q,
                                                 const float* __restrict__ Kin,
                                                 const float* __restrict__ V,
                                                 const float* __restrict__ Wq,
                                                 const float* __restrict__ Wk,
                                                 const float* __restrict__ Wv,
                                                 const float* __restrict__ coW,
                                                 const float* __restrict__ cob,
                                                 const float* __restrict__ sepb) {
    const int op = blockIdx.z;
    const float* A = (op == 0) ? Q : (op == 1) ? Kin : (op == 4) ? g_dw : V;
    const float* B = (op == 0) ? Wq : (op == 1) ? Wk : (op == 2) ? Wv : (op == 3) ? coW : g_pwT;
    const float* bias = (op == 3) ? cob : (op == 4) ? sepb : nullptr;
    float* C = (op == 0) ? g_mq : (op == 1) ? g_mk : (op == 2) ? g_mv : (op == 3) ? g_co : g_mkc;

    float c[2][2][4];
    tf32_gemm<false, true>(A, HID, nullptr, B, AH, HID, 64, c);

    const int t = threadIdx.x, wid = t >> 5, lane = t & 31;
    const int wm = wid >> 2, wn = wid & 3;
    const int r = lane >> 2, cl = lane & 3;
    const int bm = blockIdx.y * 64, bn = blockIdx.x * 64;
    #pragma unroll
    for (int mt = 0; mt < 2; mt++)
        #pragma unroll
        for (int nt = 0; nt < 2; nt++) {
            int gr = bm + wm * 32 + mt * 16 + r;
            int gc = bn + wn * 16 + nt * 8 + 2 * cl;
            float b0 = bias ? bias[gc] : 0.f, b1 = bias ? bias[gc + 1] : 0.f;
            *reinterpret_cast<float2*>(&C[(size_t)gr * AH + gc]) =
                make_float2(c[mt][nt][0] + b0, c[mt][nt][1] + b1);
            *reinterpret_cast<float2*>(&C[(size_t)(gr + 8) * AH + gc]) =
                make_float2(c[mt][nt][2] + b0, c[mt][nt][3] + b1);
        }
}

// ---- ck GEMM: A = mkc*mq (fused), B = ck_W [384x54], N=54 ----
__global__ __launch_bounds__(256) void k_ck_tc(const float* __restrict__ ckW,
                                               const float* __restrict__ ckb) {
    float c[2][2][4];
    tf32_gemm<false, false>(g_mkc, AH, g_mq, ckW, NCK, AH, NCK, c);
    const int t = threadIdx.x, wid = t >> 5, lane = t & 31;
    const int wm = wid >> 2, wn = wid & 3;
    const int r = lane >> 2, cl = lane & 3;
    const int bm = blockIdx.y * 64;
    #pragma unroll
    for (int mt = 0; mt < 2; mt++)
        #pragma unroll
        for (int nt = 0; nt < 2; nt++) {
            int gr = bm + wm * 32 + mt * 16 + r;
            int gc = wn * 16 + nt * 8 + 2 * cl;
            if (gc + 1 < NCK) {
                g_ck[(size_t)gr * NCK + gc]     = c[mt][nt][0] + ckb[gc];
                g_ck[(size_t)gr * NCK + gc + 1] = c[mt][nt][1] + ckb[gc + 1];
                g_ck[(size_t)(gr + 8) * NCK + gc]     = c[mt][nt][2] + ckb[gc];
                g_ck[(size_t)(gr + 8) * NCK + gc + 1] = c[mt][nt][3] + ckb[gc + 1];
            }
        }
}

// ---- QK^T (tf32): scores = q @ k^T / 8 ----
__global__ __launch_bounds__(256) void qk_tc() {
    const int bh = blockIdx.z;
    const int b = bh / NH, h = bh % NH;
    const float* qb = g_mq + (size_t)b * SS * AH + h * HD;
    const float* kb = g_mk + (size_t)b * SS * AH + h * HD;
    float c[2][2][4];
    tf32_gemm<true, false>(qb, AH, nullptr, kb, AH, HD, 64, c);
    const int t = threadIdx.x, wid = t >> 5, lane = t & 31;
    const int wm = wid >> 2, wn = wid & 3;
    const int r = lane >> 2, cl = lane & 3;
    const int bm = blockIdx.y * 64, bn = blockIdx.x * 64;
    float* crow = g_sc + (size_t)bh * SS * SS;
    #pragma unroll
    for (int mt = 0; mt < 2; mt++)
        #pragma unroll
        for (int nt = 0; nt < 2; nt++) {
            int gr = bm + wm * 32 + mt * 16 + r;
            int gc = bn + wn * 16 + nt * 8 + 2 * cl;
            *reinterpret_cast<float2*>(&crow[(size_t)gr * SS + gc]) =
                make_float2(c[mt][nt][0] * 0.125f, c[mt][nt][1] * 0.125f);
            *reinterpret_cast<float2*>(&crow[(size_t)(gr + 8) * SS + gc]) =
                make_float2(c[mt][nt][2] * 0.125f, c[mt][nt][3] * 0.125f);
        }
}

// ---- P@V (tf32): ctx -> out[:, 0:AH] ----
__global__ __launch_bounds__(256) void pv_tc(float* __restrict__ out) {
    const int bh = blockIdx.z;
    const int b = bh / NH, h = bh % NH;
    const float* P = g_sc + (size_t)bh * SS * SS;
    const float* vb = g_mv + (size_t)b * SS * AH + h * HD;
    float c[2][2][4];
    tf32_gemm<false, false>(P, SS, nullptr, vb, AH, SS, 64, c);
    const int t = threadIdx.x, wid = t >> 5, lane = t & 31;
    const int wm = wid >> 2, wn = wid & 3;
    const int r = lane >> 2, cl = lane & 3;
    const int bm = blockIdx.y * 64;
    #pragma unroll
    for (int mt = 0; mt < 2; mt++)
        #pragma unroll
        for (int nt = 0; nt < 2; nt++) {
            int gr = bm + wm * 32 + mt * 16 + r;
            int gc = wn * 16 + nt * 8 + 2 * cl;
            size_t ro = (size_t)(b * SS + gr) * OUTW + h * HD + gc;
            *reinterpret_cast<float2*>(&out[ro]) = make_float2(c[mt][nt][0], c[mt][nt][1]);
            *reinterpret_cast<float2*>(&out[ro + (size_t)8 * OUTW]) = make_float2(c[mt][nt][2], c[mt][nt][3]);
        }
}

// ---------------- depthwise conv ----------------
__global__ void dwconv_kernel(const float* __restrict__ Kin, const float* __restrict__ dww) {
    int idx = blockIdx.x * blockDim.x + threadIdx.x;
    if (idx >= BSROWS * HID) return;
    int c = idx % HID;
    int s = (idx / HID) & (SS - 1);
    int b = idx / (HID * SS);
    float acc = 0.f;
    #pragma unroll
    for (int t = 0; t < KS; t++) {
        int sj = s + t - PAD;
        if (sj >= 0 && sj < SS)
            acc += Kin[((size_t)(b * SS + sj)) * HID + c] * dww[c * KS + t];
    }
    g_dw[idx] = acc;
}

__global__ void transpose_pw(const float* __restrict__ pw) {
    int idx = blockIdx.x * blockDim.x + threadIdx.x;
    if (idx >= HID * AH) return;
    int o = idx % AH, c = idx / AH;
    g_pwT[idx] = pw[(size_t)o * HID + c];
}

// ---------------- dynamic-span conv output ----------------
__global__ __launch_bounds__(384) void convout_kernel(float* __restrict__ out) {
    int bs = blockIdx.x;
    int tid = threadIdx.x;
    int h = tid >> 6, d = tid & 63;
    const float* cr = g_ck + (size_t)bs * NCK + h * KS;
    float w[KS];
    float mx = -3.4e38f;
    #pragma unroll
    for (int t = 0; t < KS; t++) { w[t] = cr[t]; mx = fmaxf(mx, w[t]); }
    float sm = 0.f;
    #pragma unroll
    for (int t = 0; t < KS; t++) { w[t] = __expf(w[t] - mx); sm += w[t]; }
    float inv = 1.f / sm;
    int b = bs >> 10, s = bs & (SS - 1);
    float acc = 0.f;
    #pragma unroll
    for (int t = 0; t < KS; t++) {
        int sj = s + t - PAD;
        if (sj >= 0 && sj < SS)
            acc += w[t] * inv * g_co[((size_t)(b * SS + sj)) * AH + h * HD + d];
    }
    out[(size_t)bs * OUTW + AH + h * HD + d] = acc;
}

// ---------------- td softmax ----------------
__global__ __launch_bounds__(256) void tdsm_kernel(const float* __restrict__ td, const int* __restrict__ mask) {
    int b = blockIdx.x;
    int tid = threadIdx.x;
    __shared__ float s_red[256];
    const float* tr = td + b * SS;
    const int* mr = mask + b * SS;
    float ss = 0.f;
    for (int j = tid; j < SS; j += 256) { float v = tr[j]; ss += v * v; }
    s_red[tid] = ss; __syncthreads();
    for (int off = 128; off > 0; off >>= 1) { if (tid < off) s_red[tid] += s_red[tid + off]; __syncthreads(); }
    float inv = 1.f / fmaxf(sqrtf(s_red[0]), 1e-12f);
    __syncthreads();
    float mx = -3.4e38f;
    for (int j = tid; j < SS; j += 256) { float v = mr[j] ? tr[j] * inv : -1e4f; mx = fmaxf(mx, v); }
    s_red[tid] = mx; __syncthreads();
    for (int off = 128; off > 0; off >>= 1) { if (tid < off) s_red[tid] = fmaxf(s_red[tid], s_red[tid + off]); __syncthreads(); }
    mx = s_red[0]; __syncthreads();
    float es = 0.f;
    for (int j = tid; j < SS; j += 256) { float v = mr[j] ? tr[j] * inv : -1e4f; es += __expf(v - mx); }
    s_red[tid] = es; __syncthreads();
    for (int off = 128; off > 0; off >>= 1) { if (tid < off) s_red[tid] += s_red[tid + off]; __syncthreads(); }
    es = s_red[0]; __syncthreads();
    float einv = 1.f / es;
    for (int j = tid; j < SS; j += 256) {
        float v = mr[j] ? tr[j] * inv : -1e4f;
        g_tdsm[b * SS + j] = __expf(v - mx) * einv;
    }
}

// ---------------- per-row pass (register/shuffle) ----------------
__global__ __launch_bounds__(256) void row_kernel(const int* __restrict__ mask,
                                                  const float* __restrict__ gammas) {
    const int tid = threadIdx.x;
    const int lane = tid & 31, w = tid >> 5;
    const int row = blockIdx.x;
    const int i = row & (SS - 1);
    const int bh = row >> 10;
    const int h = bh % NH;
    const int b = bh / NH;

    __shared__ float s8[8];
    __shared__ float swarp[8];

    float* srow = g_sc + (size_t)row * SS;
    const int base = tid * 4;

    float4 sc = *reinterpret_cast<const float4*>(&srow[base]);
    int4  mk = *reinterpret_cast<const int4*>(&mask[b * SS + base]);

    float v0 = mk.x ? sc.x : -1e8f;
    float v1 = mk.y ? sc.y : -1e8f;
    float v2 = mk.z ? sc.z : -1e8f;
    float v3 = mk.w ? sc.w : -1e8f;
    float mx = fmaxf(fmaxf(v0, v1), fmaxf(v2, v3));
    #pragma unroll
    for (int o = 16; o > 0; o >>= 1) mx = fmaxf(mx, __shfl_xor_sync(0xffffffffu, mx, o));
    if (lane == 0) s8[w] = mx;
    __syncthreads();
    mx = fmaxf(fmaxf(fmaxf(s8[0], s8[1]), fmaxf(s8[2], s8[3])),
               fmaxf(fmaxf(s8[4], s8[5]), fmaxf(s8[6], s8[7])));

    float e0 = mk.x ? __expf(sc.x - mx) : 0.f;
    float e1 = mk.y ? __expf(sc.y - mx) : 0.f;
    float e2 = mk.z ? __expf(sc.z - mx) : 0.f;
    float e3 = mk.w ? __expf(sc.w - mx) : 0.f;
    float sm = (e0 + e1) + (e2 + e3);
    #pragma unroll
    for (int o = 16; o > 0; o >>= 1) sm += __shfl_xor_sync(0xffffffffu, sm, o);
    __syncthreads();
    if (lane == 0) s8[w] = sm;
    __syncthreads();
    sm = ((s8[0] + s8[1]) + (s8[2] + s8[3])) + ((s8[4] + s8[5]) + (s8[6] + s8[7]));
    float inv = (sm > 0.f) ? (1.f / sm) : 0.f;

    float c0 = e0 * inv;
    float c1 = c0 + e1 * inv;
    float c2 = c1 + e2 * inv;
    float c3 = c2 + e3 * inv;
    float x = c3;
    #pragma unroll
    for (int o = 1; o < 32; o <<= 1) {
        float y = __shfl_up_sync(0xffffffffu, x, o);
        if (lane >= o) x += y;
    }
    if (lane == 31) swarp[w] = x;
    __syncthreads();
    if (tid < 8) {
        float t = swarp[tid];
        #pragma unroll
        for (int o = 1; o < 8; o <<= 1) {
            float y = __shfl_up_sync(0xffu, t, o);
            if (tid >= o) t += y;
        }
        swarp[tid] = t;
    }
    __syncthreads();
    float wpref = w ? swarp[w - 1] : 0.f;
    float total = swarp[7];
    float pref = x + wpref - c3;

    float cums[4] = {pref + c0, pref + c1, pref + c2, pref + c3};

    const float gamma_h = -log1pf(__expf(gammas[h]));
    float4 tdv = *reinterpret_cast<const float4*>(&g_tdsm[b * SS + base]);
    float nv[4];
    float scs[4] = {sc.x, sc.y, sc.z, sc.w};
    int mks[4] = {mk.x, mk.y, mk.z, mk.w};
    float tds[4] = {tdv.x, tdv.y, tdv.z, tdv.w};
    float mx2 = -3.4e38f;
    #pragma unroll
    for (int u = 0; u < 4; u++) {
        int j = base + u;
        float rem = total - cums[u];
        float posd = fabsf((float)(j - i));
        float ds = sqrtf(fmaxf(rem * posd, 0.f));
        float te = __expf(ds * gamma_h);
        te = fminf(fmaxf(te, 1e-5f), 1e5f);
        if (j < i) te -= tds[u];
        float v = mks[u] ? scs[u] * te : -1e8f;
        nv[u] = v;
        mx2 = fmaxf(mx2, v);
    }
    #pragma unroll
    for (int o = 16; o > 0; o >>= 1) mx2 = fmaxf(mx2, __shfl_xor_sync(0xffffffffu, mx2, o));
    __syncthreads();
    if (lane == 0) s8[w] = mx2;
    __syncthreads();
    mx2 = fmaxf(fmaxf(fmaxf(s8[0], s8[1]), fmaxf(s8[2], s8[3])),
                fmaxf(fmaxf(s8[4], s8[5]), fmaxf(s8[6], s8[7])));

    float f0 = __expf(nv[0] - mx2);
    float f1 = __expf(nv[1] - mx2);
    float f2 = __expf(nv[2] - mx2);
    float f3 = __expf(nv[3] - mx2);
    float sm2 = (f0 + f1) + (f2 + f3);
    #pragma unroll
    for (int o = 16; o > 0; o >>= 1) sm2 += __shfl_xor_sync(0xffffffffu, sm2, o);
    __syncthreads();
    if (lane == 0) s8[w] = sm2;
    __syncthreads();
    sm2 = ((s8[0] + s8[1]) + (s8[2] + s8[3])) + ((s8[4] + s8[5]) + (s8[6] + s8[7]));
    float inv2 = 1.f / sm2;

    float4 outv = make_float4(f0 * inv2, f1 * inv2, f2 * inv2, f3 * inv2);
    *reinterpret_cast<float4*>(&srow[base]) = outv;
}

// ---------------- launch ----------------
extern "C" void kernel_launch(void* const* d_in, const int* in_sizes, int n_in,
                              void* d_out, int out_size) {
    const float* Q     = (const float*)d_in[0];
    const float* Kin   = (const float*)d_in[1];
    const float* V     = (const float*)d_in[2];
    const float* td    = (const float*)d_in[3];
    const int*   mask  = (const int*)  d_in[4];
    const float* Wq    = (const float*)d_in[5];
    const float* Wk    = (const float*)d_in[6];
    const float* Wv    = (const float*)d_in[7];
    const float* dw_w  = (const float*)d_in[8];
    const float* pw_w  = (const float*)d_in[9];
    const float* sep_b = (const float*)d_in[10];
    const float* ck_W  = (const float*)d_in[11];
    const float* ck_b  = (const float*)d_in[12];
    const float* co_W  = (const float*)d_in[13];
    const float* co_b  = (const float*)d_in[14];
    const float* gammas= (const float*)d_in[15];
    float* out = (float*)d_out;

    dwconv_kernel<<<(BSROWS * HID + 255) / 256, 256>>>(Kin, dw_w);
    transpose_pw<<<(HID * AH + 255) / 256, 256>>>(pw_w);
    tdsm_kernel<<<SB, 256>>>(td, mask);

    // all five 768-K GEMMs, tensor cores, one launch: grid 6x64x5
    k_proj_tc<<<dim3(AH/64, BSROWS/64, 5), 256>>>(Q, Kin, V, Wq, Wk, Wv, co_W, co_b, sep_b);

    k_ck_tc<<<dim3(1, BSROWS/64), 256>>>(ck_W, ck_b);
    convout_kernel<<<BSROWS, 384>>>(out);

    qk_tc<<<dim3(SS/64, SS/64, NBH), 256>>>();
    row_kernel<<<NBH * SS, 256>>>(mask, gammas);
    pv_tc<<<dim3(1, SS/64, NBH), 256>>>(out);
}

// round 14
// speedup vs baseline: 2.4502x; 1.2591x over previous
#include <cuda_runtime.h>
#include <cstddef>
#include <cstdint>

#define SB 4
#define SS 1024
#define HID 768
#define NH 6
#define HD 64
#define AH 384
#define KS 9
#define PAD 4
#define BSROWS (SB*SS)
#define OUTW (2*AH)
#define NBH (SB*NH)
#define NCK (NH*KS)   // 54

// ---------------- scratch ----------------
__device__ float g_mq [BSROWS*AH];
__device__ float g_mk [BSROWS*AH];
__device__ float g_mv [BSROWS*AH];
__device__ float g_co [BSROWS*AH];
__device__ float g_mkc[BSROWS*AH];
__device__ float g_dw [BSROWS*HID];
__device__ float g_ck [BSROWS*NCK];
__device__ float g_pwT[HID*AH];
__device__ float g_tdsm[SB*SS];
__device__ float g_sc [(size_t)NBH*SS*SS];   // 100.7 MB

// ---------------- tf32 mma helpers ----------------
__device__ __forceinline__ unsigned f2tf(float x) {
    unsigned r; asm("cvt.rna.tf32.f32 %0, %1;" : "=r"(r) : "f"(x)); return r;
}
__device__ __forceinline__ void mma8(float c[4], unsigned a0, unsigned a1, unsigned a2, unsigned a3,
                                     unsigned b0, unsigned b1) {
    asm volatile("mma.sync.aligned.m16n8k8.row.col.f32.tf32.tf32.f32 "
        "{%0,%1,%2,%3}, {%4,%5,%6,%7}, {%8,%9}, {%0,%1,%2,%3};"
        : "+f"(c[0]), "+f"(c[1]), "+f"(c[2]), "+f"(c[3])
        : "r"(a0), "r"(a1), "r"(a2), "r"(a3), "r"(b0), "r"(b1));
}

// ---------------- unified single-pass tf32 GEMM body ----------------
// C_tile(64x64) = A[64xK] @ B ; A row-major (lda), optional elementwise A2 multiplier.
// BT=false: B is K x N row-major (ldb). BT=true: B is N x K row-major (B^T used).
// Nb: valid N inside the 64-wide tile (<=64); OOB filled with zeros.
template<bool BT>
__device__ __forceinline__ void tf32_gemm(const float* __restrict__ A, int lda,
                                          const float* __restrict__ A2,
                                          const float* __restrict__ B, int ldb,
                                          int K, int Nb, float c[2][2][4]) {
    __shared__ unsigned AsH[64][20];
    __shared__ unsigned BsH[16][72];

    const int t = threadIdx.x;
    const int bm = blockIdx.y * 64, bn = blockIdx.x * 64;
    const int am = t >> 2, ak = (t & 3) * 4;
    const int wid = t >> 5, lane = t & 31;
    const int wm = wid >> 2, wn = wid & 3;
    const int r = lane >> 2, cl = lane & 3;

    #pragma unroll
    for (int mt = 0; mt < 2; mt++)
        #pragma unroll
        for (int nt = 0; nt < 2; nt++)
            #pragma unroll
            for (int u = 0; u < 4; u++) c[mt][nt][u] = 0.f;

    for (int k0 = 0; k0 < K; k0 += 16) {
        __syncthreads();
        // ---- A tile ----
        {
            size_t off = (size_t)(bm + am) * lda + k0 + ak;
            float4 v = *reinterpret_cast<const float4*>(A + off);
            if (A2) {
                float4 w = *reinterpret_cast<const float4*>(A2 + off);
                v.x *= w.x; v.y *= w.y; v.z *= w.z; v.w *= w.w;
            }
            uint4 h; h.x = f2tf(v.x); h.y = f2tf(v.y); h.z = f2tf(v.z); h.w = f2tf(v.w);
            *reinterpret_cast<uint4*>(&AsH[am][ak]) = h;
        }
        // ---- B tile ----
        if (!BT) {
            int bk = t >> 4, bn4 = (t & 15) * 4;
            const float* bp = B + (size_t)(k0 + bk) * ldb + bn + bn4;
            float4 v;
            if (Nb == 64) {
                v = *reinterpret_cast<const float4*>(bp);
            } else {
                v.x = (bn4 + 0 < Nb) ? bp[0] : 0.f;
                v.y = (bn4 + 1 < Nb) ? bp[1] : 0.f;
                v.z = (bn4 + 2 < Nb) ? bp[2] : 0.f;
                v.w = (bn4 + 3 < Nb) ? bp[3] : 0.f;
            }
            uint4 h; h.x = f2tf(v.x); h.y = f2tf(v.y); h.z = f2tf(v.z); h.w = f2tf(v.w);
            *reinterpret_cast<uint4*>(&BsH[bk][bn4]) = h;
        } else {
            int n = t >> 2, k4 = (t & 3) * 4;
            float4 v = *reinterpret_cast<const float4*>(B + (size_t)(bn + n) * ldb + k0 + k4);
            BsH[k4 + 0][n] = f2tf(v.x);
            BsH[k4 + 1][n] = f2tf(v.y);
            BsH[k4 + 2][n] = f2tf(v.z);
            BsH[k4 + 3][n] = f2tf(v.w);
        }
        __syncthreads();

        #pragma unroll
        for (int k8 = 0; k8 < 16; k8 += 8) {
            unsigned aH[2][4], bH[2][2];
            #pragma unroll
            for (int mt = 0; mt < 2; mt++) {
                int mr = wm * 32 + mt * 16 + r;
                aH[mt][0] = AsH[mr][k8 + cl];
                aH[mt][1] = AsH[mr + 8][k8 + cl];
                aH[mt][2] = AsH[mr][k8 + cl + 4];
                aH[mt][3] = AsH[mr + 8][k8 + cl + 4];
            }
            #pragma unroll
            for (int nt = 0; nt < 2; nt++) {
                int bc = wn * 16 + nt * 8 + r;
                bH[nt][0] = BsH[k8 + cl][bc];
                bH[nt][1] = BsH[k8 + cl + 4][bc];
            }
            #pragma unroll
            for (int mt = 0; mt < 2; mt++)
                #pragma unroll
                for (int nt = 0; nt < 2; nt++)
                    mma8(c[mt][nt], aH[mt][0], aH[mt][1], aH[mt][2], aH[mt][3], bH[nt][0], bH[nt][1]);
        }
    }
}

// ---- 5 projection GEMMs (single-pass tf32): op = blockIdx.z ----
__global__ __launch_bounds__(256) void k_proj_tc(const float* __restrict__ Q,
                                                 const float* __restrict__ Kin,
                                                 const float* __restrict__ V,
                                                 const float* __restrict__ Wq,
                                                 const float* __restrict__ Wk,
                                                 const float* __restrict__ Wv,
                                                 const float* __restrict__ coW,
                                                 const float* __restrict__ cob,
                                                 const float* __restrict__ sepb) {
    const int op = blockIdx.z;
    const float* A = (op == 0) ? Q : (op == 1) ? Kin : (op == 4) ? g_dw : V;
    const float* B = (op == 0) ? Wq : (op == 1) ? Wk : (op == 2) ? Wv : (op == 3) ? coW : g_pwT;
    const float* bias = (op == 3) ? cob : (op == 4) ? sepb : nullptr;
    float* C = (op == 0) ? g_mq : (op == 1) ? g_mk : (op == 2) ? g_mv : (op == 3) ? g_co : g_mkc;

    float c[2][2][4];
    tf32_gemm<false>(A, HID, nullptr, B, AH, HID, 64, c);

    const int t = threadIdx.x, wid = t >> 5, lane = t & 31;
    const int wm = wid >> 2, wn = wid & 3;
    const int r = lane >> 2, cl = lane & 3;
    const int bm = blockIdx.y * 64, bn = blockIdx.x * 64;
    #pragma unroll
    for (int mt = 0; mt < 2; mt++)
        #pragma unroll
        for (int nt = 0; nt < 2; nt++) {
            int gr = bm + wm * 32 + mt * 16 + r;
            int gc = bn + wn * 16 + nt * 8 + 2 * cl;
            float b0 = bias ? bias[gc] : 0.f, b1 = bias ? bias[gc + 1] : 0.f;
            *reinterpret_cast<float2*>(&C[(size_t)gr * AH + gc]) =
                make_float2(c[mt][nt][0] + b0, c[mt][nt][1] + b1);
            *reinterpret_cast<float2*>(&C[(size_t)(gr + 8) * AH + gc]) =
                make_float2(c[mt][nt][2] + b0, c[mt][nt][3] + b1);
        }
}

// ---- ck GEMM: A = mkc*mq (fused), B = ck_W [384x54], N=54 ----
__global__ __launch_bounds__(256) void k_ck_tc(const float* __restrict__ ckW,
                                               const float* __restrict__ ckb) {
    float c[2][2][4];
    tf32_gemm<false>(g_mkc, AH, g_mq, ckW, NCK, AH, NCK, c);
    const int t = threadIdx.x, wid = t >> 5, lane = t & 31;
    const int wm = wid >> 2, wn = wid & 3;
    const int r = lane >> 2, cl = lane & 3;
    const int bm = blockIdx.y * 64;
    #pragma unroll
    for (int mt = 0; mt < 2; mt++)
        #pragma unroll
        for (int nt = 0; nt < 2; nt++) {
            int gr = bm + wm * 32 + mt * 16 + r;
            int gc = wn * 16 + nt * 8 + 2 * cl;
            if (gc + 1 < NCK) {
                g_ck[(size_t)gr * NCK + gc]     = c[mt][nt][0] + ckb[gc];
                g_ck[(size_t)gr * NCK + gc + 1] = c[mt][nt][1] + ckb[gc + 1];
                g_ck[(size_t)(gr + 8) * NCK + gc]     = c[mt][nt][2] + ckb[gc];
                g_ck[(size_t)(gr + 8) * NCK + gc + 1] = c[mt][nt][3] + ckb[gc + 1];
            }
        }
}

// ---- QK^T (tf32): scores = q @ k^T / 8 ----
__global__ __launch_bounds__(256) void qk_tc() {
    const int bh = blockIdx.z;
    const int b = bh / NH, h = bh % NH;
    const float* qb = g_mq + (size_t)b * SS * AH + h * HD;
    const float* kb = g_mk + (size_t)b * SS * AH + h * HD;
    float c[2][2][4];
    tf32_gemm<true>(qb, AH, nullptr, kb, AH, HD, 64, c);
    const int t = threadIdx.x, wid = t >> 5, lane = t & 31;
    const int wm = wid >> 2, wn = wid & 3;
    const int r = lane >> 2, cl = lane & 3;
    const int bm = blockIdx.y * 64, bn = blockIdx.x * 64;
    float* crow = g_sc + (size_t)bh * SS * SS;
    #pragma unroll
    for (int mt = 0; mt < 2; mt++)
        #pragma unroll
        for (int nt = 0; nt < 2; nt++) {
            int gr = bm + wm * 32 + mt * 16 + r;
            int gc = bn + wn * 16 + nt * 8 + 2 * cl;
            *reinterpret_cast<float2*>(&crow[(size_t)gr * SS + gc]) =
                make_float2(c[mt][nt][0] * 0.125f, c[mt][nt][1] * 0.125f);
            *reinterpret_cast<float2*>(&crow[(size_t)(gr + 8) * SS + gc]) =
                make_float2(c[mt][nt][2] * 0.125f, c[mt][nt][3] * 0.125f);
        }
}

// ---- P@V (tf32): ctx -> out[:, 0:AH] ----
__global__ __launch_bounds__(256) void pv_tc(float* __restrict__ out) {
    const int bh = blockIdx.z;
    const int b = bh / NH, h = bh % NH;
    const float* P = g_sc + (size_t)bh * SS * SS;
    const float* vb = g_mv + (size_t)b * SS * AH + h * HD;
    float c[2][2][4];
    tf32_gemm<false>(P, SS, nullptr, vb, AH, SS, 64, c);
    const int t = threadIdx.x, wid = t >> 5, lane = t & 31;
    const int wm = wid >> 2, wn = wid & 3;
    const int r = lane >> 2, cl = lane & 3;
    const int bm = blockIdx.y * 64;
    #pragma unroll
    for (int mt = 0; mt < 2; mt++)
        #pragma unroll
        for (int nt = 0; nt < 2; nt++) {
            int gr = bm + wm * 32 + mt * 16 + r;
            int gc = wn * 16 + nt * 8 + 2 * cl;
            size_t ro = (size_t)(b * SS + gr) * OUTW + h * HD + gc;
            *reinterpret_cast<float2*>(&out[ro]) = make_float2(c[mt][nt][0], c[mt][nt][1]);
            *reinterpret_cast<float2*>(&out[ro + (size_t)8 * OUTW]) = make_float2(c[mt][nt][2], c[mt][nt][3]);
        }
}

// ---------------- depthwise conv ----------------
__global__ void dwconv_kernel(const float* __restrict__ Kin, const float* __restrict__ dww) {
    int idx = blockIdx.x * blockDim.x + threadIdx.x;
    if (idx >= BSROWS * HID) return;
    int c = idx % HID;
    int s = (idx / HID) & (SS - 1);
    int b = idx / (HID * SS);
    float acc = 0.f;
    #pragma unroll
    for (int t = 0; t < KS; t++) {
        int sj = s + t - PAD;
        if (sj >= 0 && sj < SS)
            acc += Kin[((size_t)(b * SS + sj)) * HID + c] * dww[c * KS + t];
    }
    g_dw[idx] = acc;
}

__global__ void transpose_pw(const float* __restrict__ pw) {
    int idx = blockIdx.x * blockDim.x + threadIdx.x;
    if (idx >= HID * AH) return;
    int o = idx % AH, c = idx / AH;
    g_pwT[idx] = pw[(size_t)o * HID + c];
}

// ---------------- dynamic-span conv output ----------------
__global__ __launch_bounds__(384) void convout_kernel(float* __restrict__ out) {
    int bs = blockIdx.x;
    int tid = threadIdx.x;
    int h = tid >> 6, d = tid & 63;
    const float* cr = g_ck + (size_t)bs * NCK + h * KS;
    float w[KS];
    float mx = -3.4e38f;
    #pragma unroll
    for (int t = 0; t < KS; t++) { w[t] = cr[t]; mx = fmaxf(mx, w[t]); }
    float sm = 0.f;
    #pragma unroll
    for (int t = 0; t < KS; t++) { w[t] = __expf(w[t] - mx); sm += w[t]; }
    float inv = 1.f / sm;
    int b = bs >> 10, s = bs & (SS - 1);
    float acc = 0.f;
    #pragma unroll
    for (int t = 0; t < KS; t++) {
        int sj = s + t - PAD;
        if (sj >= 0 && sj < SS)
            acc += w[t] * inv * g_co[((size_t)(b * SS + sj)) * AH + h * HD + d];
    }
    out[(size_t)bs * OUTW + AH + h * HD + d] = acc;
}

// ---------------- td softmax ----------------
__global__ __launch_bounds__(256) void tdsm_kernel(const float* __restrict__ td, const int* __restrict__ mask) {
    int b = blockIdx.x;
    int tid = threadIdx.x;
    __shared__ float s_red[256];
    const float* tr = td + b * SS;
    const int* mr = mask + b * SS;
    float ss = 0.f;
    for (int j = tid; j < SS; j += 256) { float v = tr[j]; ss += v * v; }
    s_red[tid] = ss; __syncthreads();
    for (int off = 128; off > 0; off >>= 1) { if (tid < off) s_red[tid] += s_red[tid + off]; __syncthreads(); }
    float inv = 1.f / fmaxf(sqrtf(s_red[0]), 1e-12f);
    __syncthreads();
    float mx = -3.4e38f;
    for (int j = tid; j < SS; j += 256) { float v = mr[j] ? tr[j] * inv : -1e4f; mx = fmaxf(mx, v); }
    s_red[tid] = mx; __syncthreads();
    for (int off = 128; off > 0; off >>= 1) { if (tid < off) s_red[tid] = fmaxf(s_red[tid], s_red[tid + off]); __syncthreads(); }
    mx = s_red[0]; __syncthreads();
    float es = 0.f;
    for (int j = tid; j < SS; j += 256) { float v = mr[j] ? tr[j] * inv : -1e4f; es += __expf(v - mx); }
    s_red[tid] = es; __syncthreads();
    for (int off = 128; off > 0; off >>= 1) { if (tid < off) s_red[tid] += s_red[tid + off]; __syncthreads(); }
    es = s_red[0]; __syncthreads();
    float einv = 1.f / es;
    for (int j = tid; j < SS; j += 256) {
        float v = mr[j] ? tr[j] * inv : -1e4f;
        g_tdsm[b * SS + j] = __expf(v - mx) * einv;
    }
}

// ---------------- per-row pass (register/shuffle) ----------------
__global__ __launch_bounds__(256) void row_kernel(const int* __restrict__ mask,
                                                  const float* __restrict__ gammas) {
    const int tid = threadIdx.x;
    const int lane = tid & 31, w = tid >> 5;
    const int row = blockIdx.x;
    const int i = row & (SS - 1);
    const int bh = row >> 10;
    const int h = bh % NH;
    const int b = bh / NH;

    __shared__ float s8[8];
    __shared__ float swarp[8];

    float* srow = g_sc + (size_t)row * SS;
    const int base = tid * 4;

    float4 sc = *reinterpret_cast<const float4*>(&srow[base]);
    int4  mk = *reinterpret_cast<const int4*>(&mask[b * SS + base]);

    float v0 = mk.x ? sc.x : -1e8f;
    float v1 = mk.y ? sc.y : -1e8f;
    float v2 = mk.z ? sc.z : -1e8f;
    float v3 = mk.w ? sc.w : -1e8f;
    float mx = fmaxf(fmaxf(v0, v1), fmaxf(v2, v3));
    #pragma unroll
    for (int o = 16; o > 0; o >>= 1) mx = fmaxf(mx, __shfl_xor_sync(0xffffffffu, mx, o));
    if (lane == 0) s8[w] = mx;
    __syncthreads();
    mx = fmaxf(fmaxf(fmaxf(s8[0], s8[1]), fmaxf(s8[2], s8[3])),
               fmaxf(fmaxf(s8[4], s8[5]), fmaxf(s8[6], s8[7])));

    float e0 = mk.x ? __expf(sc.x - mx) : 0.f;
    float e1 = mk.y ? __expf(sc.y - mx) : 0.f;
    float e2 = mk.z ? __expf(sc.z - mx) : 0.f;
    float e3 = mk.w ? __expf(sc.w - mx) : 0.f;
    float sm = (e0 + e1) + (e2 + e3);
    #pragma unroll
    for (int o = 16; o > 0; o >>= 1) sm += __shfl_xor_sync(0xffffffffu, sm, o);
    __syncthreads();
    if (lane == 0) s8[w] = sm;
    __syncthreads();
    sm = ((s8[0] + s8[1]) + (s8[2] + s8[3])) + ((s8[4] + s8[5]) + (s8[6] + s8[7]));
    float inv = (sm > 0.f) ? (1.f / sm) : 0.f;

    float c0 = e0 * inv;
    float c1 = c0 + e1 * inv;
    float c2 = c1 + e2 * inv;
    float c3 = c2 + e3 * inv;
    float x = c3;
    #pragma unroll
    for (int o = 1; o < 32; o <<= 1) {
        float y = __shfl_up_sync(0xffffffffu, x, o);
        if (lane >= o) x += y;
    }
    if (lane == 31) swarp[w] = x;
    __syncthreads();
    if (tid < 8) {
        float t = swarp[tid];
        #pragma unroll
        for (int o = 1; o < 8; o <<= 1) {
            float y = __shfl_up_sync(0xffu, t, o);
            if (tid >= o) t += y;
        }
        swarp[tid] = t;
    }
    __syncthreads();
    float wpref = w ? swarp[w - 1] : 0.f;
    float total = swarp[7];
    float pref = x + wpref - c3;

    float cums[4] = {pref + c0, pref + c1, pref + c2, pref + c3};

    const float gamma_h = -log1pf(__expf(gammas[h]));
    float4 tdv = *reinterpret_cast<const float4*>(&g_tdsm[b * SS + base]);
    float nv[4];
    float scs[4] = {sc.x, sc.y, sc.z, sc.w};
    int mks[4] = {mk.x, mk.y, mk.z, mk.w};
    float tds[4] = {tdv.x, tdv.y, tdv.z, tdv.w};
    float mx2 = -3.4e38f;
    #pragma unroll
    for (int u = 0; u < 4; u++) {
        int j = base + u;
        float rem = total - cums[u];
        float posd = fabsf((float)(j - i));
        float ds = sqrtf(fmaxf(rem * posd, 0.f));
        float te = __expf(ds * gamma_h);
        te = fminf(fmaxf(te, 1e-5f), 1e5f);
        if (j < i) te -= tds[u];
        float v = mks[u] ? scs[u] * te : -1e8f;
        nv[u] = v;
        mx2 = fmaxf(mx2, v);
    }
    #pragma unroll
    for (int o = 16; o > 0; o >>= 1) mx2 = fmaxf(mx2, __shfl_xor_sync(0xffffffffu, mx2, o));
    __syncthreads();
    if (lane == 0) s8[w] = mx2;
    __syncthreads();
    mx2 = fmaxf(fmaxf(fmaxf(s8[0], s8[1]), fmaxf(s8[2], s8[3])),
                fmaxf(fmaxf(s8[4], s8[5]), fmaxf(s8[6], s8[7])));

    float f0 = __expf(nv[0] - mx2);
    float f1 = __expf(nv[1] - mx2);
    float f2 = __expf(nv[2] - mx2);
    float f3 = __expf(nv[3] - mx2);
    float sm2 = (f0 + f1) + (f2 + f3);
    #pragma unroll
    for (int o = 16; o > 0; o >>= 1) sm2 += __shfl_xor_sync(0xffffffffu, sm2, o);
    __syncthreads();
    if (lane == 0) s8[w] = sm2;
    __syncthreads();
    sm2 = ((s8[0] + s8[1]) + (s8[2] + s8[3])) + ((s8[4] + s8[5]) + (s8[6] + s8[7]));
    float inv2 = 1.f / sm2;

    float4 outv = make_float4(f0 * inv2, f1 * inv2, f2 * inv2, f3 * inv2);
    *reinterpret_cast<float4*>(&srow[base]) = outv;
}

// ---------------- launch ----------------
extern "C" void kernel_launch(void* const* d_in, const int* in_sizes, int n_in,
                              void* d_out, int out_size) {
    const float* Q     = (const float*)d_in[0];
    const float* Kin   = (const float*)d_in[1];
    const float* V     = (const float*)d_in[2];
    const float* td    = (const float*)d_in[3];
    const int*   mask  = (const int*)  d_in[4];
    const float* Wq    = (const float*)d_in[5];
    const float* Wk    = (const float*)d_in[6];
    const float* Wv    = (const float*)d_in[7];
    const float* dw_w  = (const float*)d_in[8];
    const float* pw_w  = (const float*)d_in[9];
    const float* sep_b = (const float*)d_in[10];
    const float* ck_W  = (const float*)d_in[11];
    const float* ck_b  = (const float*)d_in[12];
    const float* co_W  = (const float*)d_in[13];
    const float* co_b  = (const float*)d_in[14];
    const float* gammas= (const float*)d_in[15];
    float* out = (float*)d_out;

    dwconv_kernel<<<(BSROWS * HID + 255) / 256, 256>>>(Kin, dw_w);
    transpose_pw<<<(HID * AH + 255) / 256, 256>>>(pw_w);
    tdsm_kernel<<<SB, 256>>>(td, mask);

    // all five 768-K GEMMs, tensor cores, one launch: grid 6x64x5
    k_proj_tc<<<dim3(AH/64, BSROWS/64, 5), 256>>>(Q, Kin, V, Wq, Wk, Wv, co_W, co_b, sep_b);

    k_ck_tc<<<dim3(1, BSROWS/64), 256>>>(ck_W, ck_b);
    convout_kernel<<<BSROWS, 384>>>(out);

    qk_tc<<<dim3(SS/64, SS/64, NBH), 256>>>();
    row_kernel<<<NBH * SS, 256>>>(mask, gammas);
    pv_tc<<<dim3(1, SS/64, NBH), 256>>>(out);
}